// round 6
// baseline (speedup 1.0000x reference)
#include <cuda_runtime.h>
#include <cstdint>

// Problem constants
#define B_SZ  8
#define L_SZ  256
#define D1    512
#define D2    512
#define KOUT  64

typedef unsigned long long u64;

// Scratch for stage-1 result: tmp[b][i][k][q]  (8*256*64*512 fp32 = 256 MiB)
__device__ float g_tmp[(size_t)B_SZ * L_SZ * KOUT * D2];

// ---------------------------------------------------------------------------
// Packed fp32x2 helpers (sm_103a PTX). FFMA2 doubles fp32 FMA lanes per issue.
// ---------------------------------------------------------------------------
__device__ __forceinline__ u64 pack2(float lo, float hi) {
    u64 r;
    asm("mov.b64 %0, {%1, %2};" : "=l"(r) : "f"(lo), "f"(hi));
    return r;
}
__device__ __forceinline__ void unpack2(u64 v, float& lo, float& hi) {
    asm("mov.b64 {%0, %1}, %2;" : "=f"(lo), "=f"(hi) : "l"(v));
}
__device__ __forceinline__ void fma2(u64& d, u64 a, u64 b) {
    asm("fma.rn.f32x2 %0, %1, %2, %0;" : "+l"(d) : "l"(a), "l"(b));
}

// Inner microkernel: one p-slice.
// A: 2x LDS.128 (8 floats, rows u), dup-packed for FFMA2 broadcast lanes.
// B: 2x LDS.128 loaded as longlong2 -> u64 operand pairs with ZERO pack movs.
// Total 4 LDS.128 per thread per p-step for 64 FMA lanes (min possible at 8x8).
// acc[u][v] packs (C[u][2v], C[u][2v+1]).
__device__ __forceinline__ void micro_fma(const float* __restrict__ as_row,
                                          const float* __restrict__ bs_row,
                                          int tx, int ty,
                                          u64 acc[8][4]) {
    float af[8];
    *(float4*)&af[0] = *(const float4*)&as_row[ty * 8];
    *(float4*)&af[4] = *(const float4*)&as_row[ty * 8 + 4];
    longlong2 bq0 = *(const longlong2*)&bs_row[tx * 8];      // 32B-aligned
    longlong2 bq1 = *(const longlong2*)&bs_row[tx * 8 + 4];
    u64 b2[4];
    b2[0] = (u64)bq0.x; b2[1] = (u64)bq0.y;
    b2[2] = (u64)bq1.x; b2[3] = (u64)bq1.y;
#pragma unroll
    for (int u = 0; u < 8; ++u) {
        u64 a2 = pack2(af[u], af[u]);
#pragma unroll
        for (int v = 0; v < 4; ++v) fma2(acc[u][v], a2, b2[v]);
    }
}

// ---------------------------------------------------------------------------
// Stage 1:  tmp[b,i,k,q] = sum_p x1[b,i,p] * W[k,p,q]
// Per CTA: 128(i) x 128(q) tile of the (b,k) GEMM.  NN layout.
// Double-buffered smem, 1 barrier per k-step.
// grid = (D2/128, L/128, B*KOUT)
// ---------------------------------------------------------------------------
__global__ __launch_bounds__(256)
void bilinear_stage1(const float* __restrict__ x1, const float* __restrict__ W) {
    const int t  = threadIdx.x;
    const int tx = t & 15;
    const int ty = t >> 4;

    const int bk = blockIdx.z;
    const int b  = bk >> 6;       // / KOUT
    const int k  = bk & 63;
    const int i0 = blockIdx.y * 128;
    const int q0 = blockIdx.x * 128;

    const float* A  = x1 + (size_t)b * L_SZ * D1;   // [256,512]
    const float* Bm = W  + (size_t)k * D1 * D2;     // [512,512]

    __shared__ float As[2][8][132];   // As[buf][p][i] (transposed store, pad 132)
    __shared__ float Bs[2][8][128];   // Bs[buf][p][q] (direct store)

    const int a_row = t >> 1;
    const int a_seg = (t & 1) << 2;
    const int b_p = t >> 5;
    const int b_q = (t & 31) << 2;

    u64 acc[8][4];
#pragma unroll
    for (int u = 0; u < 8; ++u)
#pragma unroll
        for (int v = 0; v < 4; ++v) acc[u][v] = 0ull;

    const float* a_ptr = A  + (size_t)(i0 + a_row) * D1 + a_seg;
    const float* b_ptr = Bm + (size_t)b_p * D2 + q0 + b_q;

    float4 av = *(const float4*)(a_ptr);
    float4 bv = *(const float4*)(b_ptr);

    int buf = 0;
    As[0][a_seg + 0][a_row] = av.x;
    As[0][a_seg + 1][a_row] = av.y;
    As[0][a_seg + 2][a_row] = av.z;
    As[0][a_seg + 3][a_row] = av.w;
    *(float4*)&Bs[0][b_p][b_q] = bv;
    __syncthreads();

    for (int p0 = 0; p0 < D1; p0 += 8) {
        const bool more = (p0 + 8 < D1);
        if (more) {   // next-tile global loads issued before compute (latency hide)
            av = *(const float4*)(a_ptr + p0 + 8);
            bv = *(const float4*)(b_ptr + (size_t)(p0 + 8) * D2);
        }

#pragma unroll
        for (int p = 0; p < 8; ++p)
            micro_fma(&As[buf][p][0], &Bs[buf][p][0], tx, ty, acc);

        if (more) {
            const int nb = buf ^ 1;
            As[nb][a_seg + 0][a_row] = av.x;
            As[nb][a_seg + 1][a_row] = av.y;
            As[nb][a_seg + 2][a_row] = av.z;
            As[nb][a_seg + 3][a_row] = av.w;
            *(float4*)&Bs[nb][b_p][b_q] = bv;
            __syncthreads();
            buf = nb;
        }
    }

    float c[8][8];
#pragma unroll
    for (int u = 0; u < 8; ++u)
#pragma unroll
        for (int v = 0; v < 4; ++v) unpack2(acc[u][v], c[u][2 * v], c[u][2 * v + 1]);

#pragma unroll
    for (int u = 0; u < 8; ++u) {
        const int i = i0 + ty * 8 + u;
        float* dst = g_tmp + (((size_t)b * L_SZ + i) * KOUT + k) * D2 + q0 + tx * 8;
        *(float4*)(dst)     = make_float4(c[u][0], c[u][1], c[u][2], c[u][3]);
        *(float4*)(dst + 4) = make_float4(c[u][4], c[u][5], c[u][6], c[u][7]);
    }
}

// ---------------------------------------------------------------------------
// Stage 2:  out[b,i,j,k] = sum_q tmp[b,i,k,q] * x2[b,j,q] + bias[k]
// Per batch b: NT GEMM rows r = i*64+k (M=16384), cols j (N=256), red q (512).
// Both operands loaded transposed into smem.  Double-buffered.
// grid = (L/128, (L*KOUT)/128, B)
// ---------------------------------------------------------------------------
__global__ __launch_bounds__(256)
void bilinear_stage2(const float* __restrict__ x2, const float* __restrict__ bias,
                     float* __restrict__ out) {
    const int t  = threadIdx.x;
    const int tx = t & 15;
    const int ty = t >> 4;

    const int b  = blockIdx.z;
    const int r0 = blockIdx.y * 128;   // r = i*64 + k
    const int j0 = blockIdx.x * 128;

    const float* A  = g_tmp + (size_t)b * L_SZ * KOUT * D2;  // rows r: stride D2
    const float* Bm = x2    + (size_t)b * L_SZ * D2;         // rows j: stride D2

    __shared__ float As[2][8][132];   // As[buf][q][r]
    __shared__ float Bs[2][8][132];   // Bs[buf][q][j]

    const int a_row = t >> 1;
    const int a_seg = (t & 1) << 2;

    u64 acc[8][4];
#pragma unroll
    for (int u = 0; u < 8; ++u)
#pragma unroll
        for (int v = 0; v < 4; ++v) acc[u][v] = 0ull;

    const float* a_ptr = A  + (size_t)(r0 + a_row) * D2 + a_seg;
    const float* b_ptr = Bm + (size_t)(j0 + a_row) * D2 + a_seg;

    float4 av = *(const float4*)(a_ptr);
    float4 bv = *(const float4*)(b_ptr);

    int buf = 0;
    As[0][a_seg + 0][a_row] = av.x;
    As[0][a_seg + 1][a_row] = av.y;
    As[0][a_seg + 2][a_row] = av.z;
    As[0][a_seg + 3][a_row] = av.w;
    Bs[0][a_seg + 0][a_row] = bv.x;
    Bs[0][a_seg + 1][a_row] = bv.y;
    Bs[0][a_seg + 2][a_row] = bv.z;
    Bs[0][a_seg + 3][a_row] = bv.w;
    __syncthreads();

    for (int q0 = 0; q0 < D2; q0 += 8) {
        const bool more = (q0 + 8 < D2);
        if (more) {
            av = *(const float4*)(a_ptr + q0 + 8);
            bv = *(const float4*)(b_ptr + q0 + 8);
        }

#pragma unroll
        for (int p = 0; p < 8; ++p)
            micro_fma(&As[buf][p][0], &Bs[buf][p][0], tx, ty, acc);

        if (more) {
            const int nb = buf ^ 1;
            As[nb][a_seg + 0][a_row] = av.x;
            As[nb][a_seg + 1][a_row] = av.y;
            As[nb][a_seg + 2][a_row] = av.z;
            As[nb][a_seg + 3][a_row] = av.w;
            Bs[nb][a_seg + 0][a_row] = bv.x;
            Bs[nb][a_seg + 1][a_row] = bv.y;
            Bs[nb][a_seg + 2][a_row] = bv.z;
            Bs[nb][a_seg + 3][a_row] = bv.w;
            __syncthreads();
            buf = nb;
        }
    }

    float c[8][8];   // c[u = row(k) dim][v = col(j) dim]
#pragma unroll
    for (int u = 0; u < 8; ++u)
#pragma unroll
        for (int v = 0; v < 4; ++v) unpack2(acc[u][v], c[u][2 * v], c[u][2 * v + 1]);

    // Thread's 8 rows are 8 consecutive k within one i.
    const int rbase = r0 + ty * 8;
    const int i  = rbase >> 6;
    const int k0 = rbase & 63;

    float bias8[8];
    *(float4*)&bias8[0] = *(const float4*)&bias[k0];
    *(float4*)&bias8[4] = *(const float4*)&bias[k0 + 4];

#pragma unroll
    for (int v = 0; v < 8; ++v) {
        const int j = j0 + tx * 8 + v;
        float* dst = out + (((size_t)b * L_SZ + i) * L_SZ + j) * KOUT + k0;
        *(float4*)(dst)     = make_float4(c[0][v] + bias8[0], c[1][v] + bias8[1],
                                          c[2][v] + bias8[2], c[3][v] + bias8[3]);
        *(float4*)(dst + 4) = make_float4(c[4][v] + bias8[4], c[5][v] + bias8[5],
                                          c[6][v] + bias8[6], c[7][v] + bias8[7]);
    }
}

// ---------------------------------------------------------------------------
// Launch: two kernels in stream order (graph-capturable, allocation-free).
// ---------------------------------------------------------------------------
extern "C" void kernel_launch(void* const* d_in, const int* in_sizes, int n_in,
                              void* d_out, int out_size) {
    const float* x1   = (const float*)d_in[0];   // [8,256,512]
    const float* x2   = (const float*)d_in[1];   // [8,256,512]
    const float* W    = (const float*)d_in[2];   // [64,512,512]
    const float* bias = (const float*)d_in[3];   // [64]
    float* out = (float*)d_out;                  // [8,256,256,64]

    dim3 g1(D2 / 128, L_SZ / 128, B_SZ * KOUT);          // (4, 2, 512)
    bilinear_stage1<<<g1, 256>>>(x1, W);

    dim3 g2(L_SZ / 128, (L_SZ * KOUT) / 128, B_SZ);      // (2, 128, 8)
    bilinear_stage2<<<g2, 256>>>(x2, bias, out);
}

// round 9
// speedup vs baseline: 1.4638x; 1.4638x over previous
#include <cuda_runtime.h>
#include <cuda_bf16.h>
#include <cstdint>

// Problem constants
#define B_SZ   8
#define L_SZ   256
#define D1     512
#define D2     512
#define KOUT   64
#define GI_SZ  (B_SZ * L_SZ)          // 2048 rows of x1/x2 across batch

typedef unsigned int u32;

// ---------------------------------------------------------------------------
// bf16 hi/lo split operand storage (device globals: allocation-free scratch)
// ---------------------------------------------------------------------------
__device__ __nv_bfloat16 g_x1h[(size_t)GI_SZ * D1];
__device__ __nv_bfloat16 g_x1l[(size_t)GI_SZ * D1];
__device__ __nv_bfloat16 g_x2h[(size_t)GI_SZ * D2];
__device__ __nv_bfloat16 g_x2l[(size_t)GI_SZ * D2];
__device__ __nv_bfloat16 g_wth[(size_t)KOUT * D2 * D1];      // Wt[k][q][p]
__device__ __nv_bfloat16 g_wtl[(size_t)KOUT * D2 * D1];
__device__ __nv_bfloat16 g_tmph[(size_t)GI_SZ * KOUT * D2];  // tmp[gi][k][q]
__device__ __nv_bfloat16 g_tmpl[(size_t)GI_SZ * KOUT * D2];

// ---------------------------------------------------------------------------
// PTX helpers — ALL base-sm_80-class instructions (no 'a'-suffix features).
// ---------------------------------------------------------------------------
__device__ __forceinline__ u32 smem_u32(const void* p) {
    u32 a;
    asm("{ .reg .u64 t; cvta.to.shared.u64 t, %1; cvt.u32.u64 %0, t; }"
        : "=r"(a) : "l"(p));
    return a;
}
__device__ __forceinline__ void cp16(u32 dst, const void* src) {
    asm volatile("cp.async.cg.shared.global [%0], [%1], 16;"
                 :: "r"(dst), "l"(src) : "memory");
}
#define CP_COMMIT() asm volatile("cp.async.commit_group;" ::: "memory")
#define CP_WAIT1()  asm volatile("cp.async.wait_group 1;" ::: "memory")
#define CP_WAIT0()  asm volatile("cp.async.wait_group 0;" ::: "memory")

__device__ __forceinline__ void ldsm4(u32 r[4], u32 addr) {
    asm volatile("ldmatrix.sync.aligned.m8n8.x4.shared.b16 {%0,%1,%2,%3}, [%4];"
                 : "=r"(r[0]), "=r"(r[1]), "=r"(r[2]), "=r"(r[3]) : "r"(addr));
}
__device__ __forceinline__ void mma_bf16(float c[4], const u32 a[4], u32 b0, u32 b1) {
    asm volatile("mma.sync.aligned.m16n8k16.row.col.f32.bf16.bf16.f32 "
                 "{%0,%1,%2,%3}, {%4,%5,%6,%7}, {%8,%9}, {%0,%1,%2,%3};"
                 : "+f"(c[0]), "+f"(c[1]), "+f"(c[2]), "+f"(c[3])
                 : "r"(a[0]), "r"(a[1]), "r"(a[2]), "r"(a[3]), "r"(b0), "r"(b1));
}

// ---------------------------------------------------------------------------
// SMEM geometry: per k-chunk (KC=32) tiles of 128 rows x 32 bf16, row stride
// 80B (32 bf16 + 8 pad) -> ldmatrix phase rows hit distinct 16B chunks
// (r*5 mod 8 is a permutation) => conflict-free LDSM. Double-buffered.
// ---------------------------------------------------------------------------
#define KC       32
#define NCH      (D1 / KC)            // 16 chunks
#define ROWB     80
#define TILE_SM  (128 * ROWB)         // 10240 B
#define BUF_SM   (4 * TILE_SM)        // Ah,Al,Bh,Bl  = 40960 B
#define SMEM_TOTAL (2 * BUF_SM)       // 81920 B

// ---------------------------------------------------------------------------
// Generic mainloop: acc[4][4][4] (mi, ni, cfrag) accumulates the 128x128 CTA
// tile of  (Ah+Al) x (Bh+Bl)^T  over K=512 with the 3-term split
// (AhBh + AhBl + AlBh).
// A*: row-major [128 x 512];  B*: row-major n x k [128 x 512].
// Warp layout: wm = wid&1 (2 x 64 rows), wn = wid>>1 (4 x 32 cols).
// ---------------------------------------------------------------------------
__device__ __forceinline__ void gemm_main(const __nv_bfloat16* __restrict__ Ah,
                                          const __nv_bfloat16* __restrict__ Al,
                                          const __nv_bfloat16* __restrict__ Bh,
                                          const __nv_bfloat16* __restrict__ Bl,
                                          char* smem, float acc[4][4][4]) {
    const u32 sb   = smem_u32(smem);
    const int t    = threadIdx.x;
    const int lane = t & 31;
    const int wid  = t >> 5;
    const int wm   = wid & 1;
    const int wn   = wid >> 1;

    // Per-thread cp.async mapping: tile tl (0..3), 2 rows, 4 x 16B segs each.
    const int tl = t >> 6;
    const int w  = t & 63;
    const __nv_bfloat16* srcp =
        ((tl == 0) ? Ah : (tl == 1) ? Al : (tl == 2) ? Bh : Bl) + (size_t)(2 * w) * D1;
    const u32 drel = (u32)(tl * TILE_SM + (2 * w) * ROWB);

    // ldmatrix base offsets (within a buffer)
    const u32 a_row = (u32)((wm * 64 + (lane & 15)) * ROWB + (lane >> 4) * 16);
    const u32 b_row = (u32)((wn * 32 + (lane & 15)) * ROWB + (lane >> 4) * 16);

#pragma unroll
    for (int mi = 0; mi < 4; ++mi)
#pragma unroll
        for (int ni = 0; ni < 4; ++ni)
#pragma unroll
            for (int cc = 0; cc < 4; ++cc) acc[mi][ni][cc] = 0.0f;

    // Preload chunk 0 into buffer 0
    {
        u32 d = sb + drel;
#pragma unroll
        for (int r = 0; r < 2; ++r)
#pragma unroll
            for (int s = 0; s < 4; ++s)
                cp16(d + r * ROWB + s * 16, srcp + (size_t)r * D1 + s * 8);
        CP_COMMIT();
    }

    for (int c = 0; c < NCH; ++c) {
        if (c + 1 < NCH) {
            u32 d = sb + ((c + 1) & 1) * BUF_SM + drel;
            const __nv_bfloat16* sp = srcp + (c + 1) * KC;
#pragma unroll
            for (int r = 0; r < 2; ++r)
#pragma unroll
                for (int s = 0; s < 4; ++s)
                    cp16(d + r * ROWB + s * 16, sp + (size_t)r * D1 + s * 8);
            CP_COMMIT();
            CP_WAIT1();
        } else {
            CP_WAIT0();
        }
        __syncthreads();

        const u32 buf = sb + (c & 1) * BUF_SM;
#pragma unroll
        for (int s2 = 0; s2 < 2; ++s2) {       // two k16 steps per 32-chunk
            const u32 kb = s2 * 32;
            u32 ah[4][4], al[4][4], bh[2][4], bl[2][4];
#pragma unroll
            for (int mi = 0; mi < 4; ++mi) {
                ldsm4(ah[mi], buf + 0 * TILE_SM + a_row + mi * 16 * ROWB + kb);
                ldsm4(al[mi], buf + 1 * TILE_SM + a_row + mi * 16 * ROWB + kb);
            }
#pragma unroll
            for (int g = 0; g < 2; ++g) {
                ldsm4(bh[g], buf + 2 * TILE_SM + b_row + g * 16 * ROWB + kb);
                ldsm4(bl[g], buf + 3 * TILE_SM + b_row + g * 16 * ROWB + kb);
            }
#pragma unroll
            for (int mi = 0; mi < 4; ++mi)
#pragma unroll
                for (int ni = 0; ni < 4; ++ni) {
                    const int g = ni >> 1, sel = ni & 1;
                    const u32 bh0 = bh[g][sel], bh1 = bh[g][sel + 2];
                    const u32 bl0 = bl[g][sel], bl1 = bl[g][sel + 2];
                    mma_bf16(acc[mi][ni], ah[mi], bh0, bh1);
                    mma_bf16(acc[mi][ni], ah[mi], bl0, bl1);
                    mma_bf16(acc[mi][ni], al[mi], bh0, bh1);
                }
        }
        __syncthreads();
    }
}

// ---------------------------------------------------------------------------
// Prepass: fp32 -> bf16 hi/lo split (elementwise), 8 elems/thread.
// ---------------------------------------------------------------------------
__global__ __launch_bounds__(256)
void conv_split(const float* __restrict__ src, __nv_bfloat16* __restrict__ hd,
                __nv_bfloat16* __restrict__ ld, int n8) {
    int i = blockIdx.x * blockDim.x + threadIdx.x;
    if (i >= n8) return;
    const float4* s = (const float4*)src + (size_t)i * 2;
    float4 v0 = s[0], v1 = s[1];
    float f[8] = { v0.x, v0.y, v0.z, v0.w, v1.x, v1.y, v1.z, v1.w };
    u32 hw[4], lw[4];
#pragma unroll
    for (int c = 0; c < 4; ++c) {
        float f0 = f[2 * c], f1 = f[2 * c + 1];
        __nv_bfloat16 h0 = __float2bfloat16_rn(f0), h1 = __float2bfloat16_rn(f1);
        __nv_bfloat16 l0 = __float2bfloat16_rn(f0 - __bfloat162float(h0));
        __nv_bfloat16 l1 = __float2bfloat16_rn(f1 - __bfloat162float(h1));
        hw[c] = (u32)__bfloat16_as_ushort(h0) | ((u32)__bfloat16_as_ushort(h1) << 16);
        lw[c] = (u32)__bfloat16_as_ushort(l0) | ((u32)__bfloat16_as_ushort(l1) << 16);
    }
    *(uint4*)(hd + (size_t)i * 8) = make_uint4(hw[0], hw[1], hw[2], hw[3]);
    *(uint4*)(ld + (size_t)i * 8) = make_uint4(lw[0], lw[1], lw[2], lw[3]);
}

// Prepass: W[k][p][q] fp32 -> Wt hi/lo [k][q][p] bf16 (transpose + split).
__global__ __launch_bounds__(256)
void conv_wt(const float* __restrict__ W) {
    __shared__ float tile[32][33];
    const int k  = blockIdx.z;
    const int p0 = blockIdx.y * 32;
    const int q0 = blockIdx.x * 32;
    const int tx = threadIdx.x & 31;
    const int ty = threadIdx.x >> 5;     // 0..7
    const float* src = W + ((size_t)k * D1 + p0) * D2 + q0;
#pragma unroll
    for (int r = 0; r < 4; ++r)
        tile[ty + r * 8][tx] = src[(size_t)(ty + r * 8) * D2 + tx];
    __syncthreads();
    const size_t dbase = ((size_t)k * D2 + q0) * D1 + p0;
#pragma unroll
    for (int r = 0; r < 4; ++r) {
        int q = ty + r * 8;
        float f = tile[tx][q];
        __nv_bfloat16 h = __float2bfloat16_rn(f);
        __nv_bfloat16 l = __float2bfloat16_rn(f - __bfloat162float(h));
        g_wth[dbase + (size_t)q * D1 + tx] = h;
        g_wtl[dbase + (size_t)q * D1 + tx] = l;
    }
}

// ---------------------------------------------------------------------------
// Stage 1: tmp[gi,k,q] = sum_p x1[gi,p] * Wt[k][q][p]
// grid = (D2/128, GI/128, KOUT)
// ---------------------------------------------------------------------------
__global__ __launch_bounds__(256, 1)
void stage1_mma() {
    extern __shared__ char smem[];
    const int t    = threadIdx.x;
    const int lane = t & 31;
    const int wid  = t >> 5;
    const int wm   = wid & 1;
    const int wn   = wid >> 1;
    const int k    = blockIdx.z;
    const int gi0  = blockIdx.y * 128;
    const int q0   = blockIdx.x * 128;

    float acc[4][4][4];
    const size_t aoff = (size_t)gi0 * D1;
    const size_t boff = ((size_t)k * D2 + q0) * D1;
    gemm_main(g_x1h + aoff, g_x1l + aoff, g_wth + boff, g_wtl + boff, smem, acc);

    // Epilogue: split fp32 accum to bf16 hi/lo -> g_tmph/g_tmpl at [gi][k][q]
#pragma unroll
    for (int mi = 0; mi < 4; ++mi) {
        const int gi_base = gi0 + wm * 64 + mi * 16 + (lane >> 2);
#pragma unroll
        for (int ni = 0; ni < 4; ++ni) {
            const int q = q0 + wn * 32 + ni * 8 + (lane & 3) * 2;
#pragma unroll
            for (int half = 0; half < 2; ++half) {
                const int gi = gi_base + half * 8;
                const float f0 = acc[mi][ni][2 * half + 0];
                const float f1 = acc[mi][ni][2 * half + 1];
                __nv_bfloat16 h0 = __float2bfloat16_rn(f0), h1 = __float2bfloat16_rn(f1);
                __nv_bfloat16 l0 = __float2bfloat16_rn(f0 - __bfloat162float(h0));
                __nv_bfloat16 l1 = __float2bfloat16_rn(f1 - __bfloat162float(h1));
                const size_t idx = ((size_t)gi * KOUT + k) * D2 + q;
                *(u32*)(g_tmph + idx) =
                    (u32)__bfloat16_as_ushort(h0) | ((u32)__bfloat16_as_ushort(h1) << 16);
                *(u32*)(g_tmpl + idx) =
                    (u32)__bfloat16_as_ushort(l0) | ((u32)__bfloat16_as_ushort(l1) << 16);
            }
        }
    }
}

// ---------------------------------------------------------------------------
// Stage 2: out[b,i,j,k] = sum_q tmp[b,i,k,q] * x2[b,j,q] + bias[k]
// rows r = i*64+kk (M), cols j (N).  grid = (L/128, (L*KOUT)/128, B)
// ---------------------------------------------------------------------------
__global__ __launch_bounds__(256, 1)
void stage2_mma(const float* __restrict__ bias, float* __restrict__ out) {
    extern __shared__ char smem[];
    const int t    = threadIdx.x;
    const int lane = t & 31;
    const int wid  = t >> 5;
    const int wm   = wid & 1;
    const int wn   = wid >> 1;
    const int b    = blockIdx.z;
    const int r0   = blockIdx.y * 128;
    const int j0   = blockIdx.x * 128;

    float acc[4][4][4];
    const size_t aoff = ((size_t)b * (L_SZ * KOUT) + r0) * D2;
    const size_t boff = ((size_t)b * L_SZ + j0) * D2;
    gemm_main(g_tmph + aoff, g_tmpl + aoff, g_x2h + boff, g_x2l + boff, smem, acc);

#pragma unroll
    for (int mi = 0; mi < 4; ++mi) {
        const int r_base = r0 + wm * 64 + mi * 16 + (lane >> 2);
#pragma unroll
        for (int half = 0; half < 2; ++half) {
            const int r  = r_base + half * 8;
            const int i  = r >> 6;
            const int kk = r & 63;
            const float bv = bias[kk];
            float* obase = out + (((size_t)b * L_SZ + i) * L_SZ) * KOUT + kk;
#pragma unroll
            for (int ni = 0; ni < 4; ++ni) {
                const int j = j0 + wn * 32 + ni * 8 + (lane & 3) * 2;
                obase[(size_t)j * KOUT]       = acc[mi][ni][2 * half + 0] + bv;
                obase[(size_t)(j + 1) * KOUT] = acc[mi][ni][2 * half + 1] + bv;
            }
        }
    }
}

// ---------------------------------------------------------------------------
// Launch (graph-capturable, allocation-free)
// ---------------------------------------------------------------------------
extern "C" void kernel_launch(void* const* d_in, const int* in_sizes, int n_in,
                              void* d_out, int out_size) {
    const float* x1   = (const float*)d_in[0];   // [8,256,512]
    const float* x2   = (const float*)d_in[1];   // [8,256,512]
    const float* W    = (const float*)d_in[2];   // [64,512,512]
    const float* bias = (const float*)d_in[3];   // [64]
    float* out = (float*)d_out;                  // [8,256,256,64]

    cudaFuncSetAttribute(stage1_mma, cudaFuncAttributeMaxDynamicSharedMemorySize, SMEM_TOTAL);
    cudaFuncSetAttribute(stage2_mma, cudaFuncAttributeMaxDynamicSharedMemorySize, SMEM_TOTAL);

    // Prepass: split inputs into bf16 hi/lo (W also transposed to [k][q][p]).
    {
        __nv_bfloat16 *x1h, *x1l, *x2h, *x2l;
        cudaGetSymbolAddress((void**)&x1h, g_x1h);
        cudaGetSymbolAddress((void**)&x1l, g_x1l);
        cudaGetSymbolAddress((void**)&x2h, g_x2h);
        cudaGetSymbolAddress((void**)&x2l, g_x2l);
        const int n8 = GI_SZ * D1 / 8;           // 131072
        conv_split<<<n8 / 256, 256>>>(x1, x1h, x1l, n8);
        conv_split<<<n8 / 256, 256>>>(x2, x2h, x2l, n8);
    }
    conv_wt<<<dim3(D2 / 32, D1 / 32, KOUT), 256>>>(W);

    stage1_mma<<<dim3(D2 / 128, GI_SZ / 128, KOUT), 256, SMEM_TOTAL>>>();
    stage2_mma<<<dim3(L_SZ / 128, (L_SZ * KOUT) / 128, B_SZ), 256, SMEM_TOTAL>>>(bias, out);
}